// round 17
// baseline (speedup 1.0000x reference)
#include <cuda_runtime.h>
#include <math.h>

#define NE 80000
#define NW 20000
#define HDIM 200
#define HV4 50            // HDIM / 4
#define NREL 16
#define NB 100
#define CAP 32            // max edges per dst bin (deg ~ Poisson(3); P(>32) ~ 0)
#define SLOPE 0.22916666666666666f

// Scratch (allocation-free rule: __device__ globals)
__device__ int g_cnt[NE];                    // per-dst live-edge count
__device__ int g_bins[(size_t)NE * CAP];     // packed (src | etype<<17) per dst

__device__ __forceinline__ float leaky(float x) {
    return x >= 0.0f ? x : x * SLOPE;
}

// ---------------------------------------------------------------------------
// 1) Bin edges by dst. Packs src+etype into one int. dst >= NE edges are dead
//    (reference keeps act[:NUM_ENTS]) — skipped.
// ---------------------------------------------------------------------------
__global__ void bin_kernel(const int* __restrict__ src,
                           const int* __restrict__ dst,
                           const int* __restrict__ etype,
                           int E) {
    int e = blockIdx.x * blockDim.x + threadIdx.x;
    if (e >= E) return;
    int d = dst[e];
    if (d < NE) {
        int slot = atomicAdd(&g_cnt[d], 1);
        if (slot < CAP)
            g_bins[(size_t)d * CAP + slot] = src[e] | (etype[e] << 17);
    }
}

// ---------------------------------------------------------------------------
// Epilogue for one node row held in (a0, a1): degree-norm + leaky +
// L2-normalize + dual store.
// ---------------------------------------------------------------------------
__device__ __forceinline__ void node_epilogue(int n, int deg, float4 a0, float4 a1,
                                              int lane, bool has2,
                                              float* __restrict__ out, int dup) {
    const float inv = (deg > 0) ? (1.0f / (float)deg) : 0.0f;
    a0.x = leaky(a0.x * inv); a0.y = leaky(a0.y * inv);
    a0.z = leaky(a0.z * inv); a0.w = leaky(a0.w * inv);
    a1.x = leaky(a1.x * inv); a1.y = leaky(a1.y * inv);
    a1.z = leaky(a1.z * inv); a1.w = leaky(a1.w * inv);

    float ss = a0.x * a0.x + a0.y * a0.y + a0.z * a0.z + a0.w * a0.w;
    if (has2)
        ss += a1.x * a1.x + a1.y * a1.y + a1.z * a1.z + a1.w * a1.w;
    #pragma unroll
    for (int o = 16; o > 0; o >>= 1)
        ss += __shfl_xor_sync(0xffffffffu, ss, o);

    const float scale = 1.0f / fmaxf(sqrtf(ss), 1e-12f);
    a0.x *= scale; a0.y *= scale; a0.z *= scale; a0.w *= scale;
    a1.x *= scale; a1.y *= scale; a1.z *= scale; a1.w *= scale;

    float4* orow = (float4*)(out + (size_t)n * HDIM);
    orow[lane] = a0;
    if (has2) orow[lane + 32] = a1;
    if (dup) {
        float4* orow2 = (float4*)(out + (size_t)NE * HDIM + (size_t)n * HDIM);
        orow2[lane] = a0;
        if (has2) orow2[lane + 32] = a1;
    }
}

// ---------------------------------------------------------------------------
// 2) Fused node kernel — TWO nodes interleaved per warp (batch 2 edges each).
//    Per-warp in-flight gather rows: min(degA,2)+min(degB,2) ≈ 4 vs 2.6 for
//    one node, with the same 8 live float4s as R4/R9. Headers (cnt/bin) of
//    both nodes also load in parallel. Weights stay de-interleaved (R9 win).
// ---------------------------------------------------------------------------
__global__ void __launch_bounds__(256)
node_kernel(const float* __restrict__ dyn,
            const float* __restrict__ words,
            const float* __restrict__ weight,
            float* __restrict__ out, int dup) {
    __shared__ float4 w_a[NREL * HV4];   // even blocks W[t][2j]
    __shared__ float4 w_b[NREL * HV4];   // odd  blocks W[t][2j+1]
    const float4* wg = (const float4*)weight;
    for (int i = threadIdx.x; i < NREL * HV4; i += blockDim.x) {
        const int t = i / HV4;
        const int j = i % HV4;
        w_a[i] = wg[t * NB + 2 * j];
        w_b[i] = wg[t * NB + 2 * j + 1];
    }
    __syncthreads();

    const int lane   = threadIdx.x & 31;
    const int warp   = (blockIdx.x * blockDim.x + threadIdx.x) >> 5;
    const int nwarps = (gridDim.x * blockDim.x) >> 5;
    const bool has2  = (lane + 32) < HV4;    // lanes 0..17 own a second chunk
    const int npairs = NE / 2;               // NE is even

    for (int p = warp; p < npairs; p += nwarps) {
        const int nA = 2 * p;
        const int nB = 2 * p + 1;

        // Independent header loads for both nodes (issued together).
        const int degA = __ldg(&g_cnt[nA]);
        const int degB = __ldg(&g_cnt[nB]);
        const int dA = min(degA, CAP);
        const int dB = min(degB, CAP);
        const int* binA = g_bins + (size_t)nA * CAP;
        const int* binB = g_bins + (size_t)nB * CAP;

        float4 aA0 = make_float4(0.f, 0.f, 0.f, 0.f);
        float4 aA1 = make_float4(0.f, 0.f, 0.f, 0.f);
        float4 aB0 = make_float4(0.f, 0.f, 0.f, 0.f);
        float4 aB1 = make_float4(0.f, 0.f, 0.f, 0.f);

        int kA = 0, kB = 0;
        while (kA < dA || kB < dB) {
            const int cA = min(2, dA - kA) > 0 ? min(2, dA - kA) : 0;
            const int cB = min(2, dB - kB) > 0 ? min(2, dB - kB) : 0;

            float4 hva[4], hvb[4];   // slots 0,1 = node A; 2,3 = node B
            int    tt[4];

            // Load phase: all gathers for both nodes issued before any FMA.
            #pragma unroll
            for (int i = 0; i < 2; i++) {
                if (i < cA) {
                    const int pk = __ldg(&binA[kA + i]);
                    const int s  = pk & 0x1FFFF;
                    tt[i] = pk >> 17;
                    const float4* hr = (const float4*)((s < NE)
                                        ? (dyn + (size_t)s * HDIM)
                                        : (words + (size_t)(s - NE) * HDIM));
                    hva[i] = __ldg(hr + lane);
                    if (has2) hvb[i] = __ldg(hr + lane + 32);
                }
            }
            #pragma unroll
            for (int i = 0; i < 2; i++) {
                if (i < cB) {
                    const int pk = __ldg(&binB[kB + i]);
                    const int s  = pk & 0x1FFFF;
                    tt[2 + i] = pk >> 17;
                    const float4* hr = (const float4*)((s < NE)
                                        ? (dyn + (size_t)s * HDIM)
                                        : (words + (size_t)(s - NE) * HDIM));
                    hva[2 + i] = __ldg(hr + lane);
                    if (has2) hvb[2 + i] = __ldg(hr + lane + 32);
                }
            }

            // Math phase (dense, de-interleaved weight loads).
            #pragma unroll
            for (int i = 0; i < 2; i++) {
                if (i < cA) {
                    const int tb = tt[i] * HV4;
                    const float4 w0 = w_a[tb + lane];
                    const float4 w1 = w_b[tb + lane];
                    aA0.x += hva[i].x * w0.x + hva[i].y * w0.z;
                    aA0.y += hva[i].x * w0.y + hva[i].y * w0.w;
                    aA0.z += hva[i].z * w1.x + hva[i].w * w1.z;
                    aA0.w += hva[i].z * w1.y + hva[i].w * w1.w;
                    if (has2) {
                        const float4 w2 = w_a[tb + lane + 32];
                        const float4 w3 = w_b[tb + lane + 32];
                        aA1.x += hvb[i].x * w2.x + hvb[i].y * w2.z;
                        aA1.y += hvb[i].x * w2.y + hvb[i].y * w2.w;
                        aA1.z += hvb[i].z * w3.x + hvb[i].w * w3.z;
                        aA1.w += hvb[i].z * w3.y + hvb[i].w * w3.w;
                    }
                }
            }
            #pragma unroll
            for (int i = 0; i < 2; i++) {
                if (i < cB) {
                    const int tb = tt[2 + i] * HV4;
                    const float4 w0 = w_a[tb + lane];
                    const float4 w1 = w_b[tb + lane];
                    aB0.x += hva[2 + i].x * w0.x + hva[2 + i].y * w0.z;
                    aB0.y += hva[2 + i].x * w0.y + hva[2 + i].y * w0.w;
                    aB0.z += hva[2 + i].z * w1.x + hva[2 + i].w * w1.z;
                    aB0.w += hva[2 + i].z * w1.y + hva[2 + i].w * w1.w;
                    if (has2) {
                        const float4 w2 = w_a[tb + lane + 32];
                        const float4 w3 = w_b[tb + lane + 32];
                        aB1.x += hvb[2 + i].x * w2.x + hvb[2 + i].y * w2.z;
                        aB1.y += hvb[2 + i].x * w2.y + hvb[2 + i].y * w2.w;
                        aB1.z += hvb[2 + i].z * w3.x + hvb[2 + i].w * w3.z;
                        aB1.w += hvb[2 + i].z * w3.y + hvb[2 + i].w * w3.w;
                    }
                }
            }

            kA += cA;
            kB += cB;
        }

        node_epilogue(nA, degA, aA0, aA1, lane, has2, out, dup);
        node_epilogue(nB, degB, aB0, aB1, lane, has2, out, dup);
    }
}

extern "C" void kernel_launch(void* const* d_in, const int* in_sizes, int n_in,
                              void* d_out, int out_size) {
    const float* dyn    = (const float*)d_in[0];
    const float* words  = (const float*)d_in[1];
    const float* weight = (const float*)d_in[2];
    const int*   src    = (const int*)d_in[3];
    const int*   dst    = (const int*)d_in[4];
    const int*   etype  = (const int*)d_in[5];
    float* out = (float*)d_out;

    const int E = in_sizes[3];
    const int dup = (out_size >= 2 * NE * HDIM) ? 1 : 0;

    void* cntp = nullptr;
    cudaGetSymbolAddress(&cntp, g_cnt);
    cudaMemsetAsync(cntp, 0, sizeof(int) * NE);

    bin_kernel<<<(E + 255) / 256, 256>>>(src, dst, etype, E);
    node_kernel<<<1184, 256>>>(dyn, words, weight, out, dup);
}